// round 2
// baseline (speedup 1.0000x reference)
#include <cuda_runtime.h>
#include <cstdint>

#define B_TOT 512
#define T_LEN 1024
#define F_DIM 128
#define U_DIM 50
#define Z_DIM 200   // 4*U
#define NB    4     // batch rows per CTA (recurrent phase)
#define TT    64    // t-tile for the Zx GEMM
#define DEPTH 8     // cp.async ring depth (recurrent phase)

// 400 MB scratch for Zx = inputs @ kernel + bias  (fp32, [B][T][200])
__device__ float g_zx[(size_t)B_TOT * T_LEN * Z_DIM];

// ---------------- packed f32x2 FMA (Blackwell) ----------------
union F2U { float2 f; unsigned long long u; };

__device__ __forceinline__ float2 fma2(float2 a, float2 b, float2 c) {
    F2U ua, ub, uc, r;
    ua.f = a; ub.f = b; uc.f = c;
    asm("fma.rn.f32x2 %0, %1, %2, %3;" : "=l"(r.u) : "l"(ua.u), "l"(ub.u), "l"(uc.u));
    return r.f;
}

// ---------------- cp.async helpers ----------------
__device__ __forceinline__ void cp16(void* smem_dst, const void* gsrc) {
    unsigned sa = (unsigned)__cvta_generic_to_shared(smem_dst);
    asm volatile("cp.async.ca.shared.global [%0], [%1], 16;\n" :: "r"(sa), "l"(gsrc));
}
__device__ __forceinline__ void cp_commit() {
    asm volatile("cp.async.commit_group;\n");
}
__device__ __forceinline__ void cp_wait_all() {
    asm volatile("cp.async.wait_group 0;\n");
}
__device__ __forceinline__ void cp_wait_7() {
    asm volatile("cp.async.wait_group 7;\n");
}

// ---------------- activations ----------------
__device__ __forceinline__ float sigm(float x) {
    return 1.f / (1.f + __expf(-x));
}
__device__ __forceinline__ float tanh_fast(float x) {
    float ax = fabsf(x);
    float e  = __expf(-2.f * ax);
    float r  = (1.f - e) / (1.f + e);
    return copysignf(r, x);
}

// ============================================================
// Phase 1: Zx[b][t][j] = sum_f inputs[b,t,f]*kernel[f,j] + bias[j]
// grid (16, 512), 400 threads.  thread tile: 4 t x 8 j, j-packed f32x2.
// ============================================================
__global__ void __launch_bounds__(400, 1) zx_gemm_kernel(
    const float* __restrict__ inputs,   // [B, T, F]
    const float* __restrict__ kernel,   // [F, 200]
    const float* __restrict__ bias)     // [200]
{
    __shared__ float xs[TT][F_DIM];     // 32 KB

    const int tid = threadIdx.x;
    const int tj  = tid % 25;           // j0 = tj*8
    const int tt  = tid / 25;           // 0..15, t base = t0 + tt*4
    const int b   = blockIdx.y;
    const int t0  = blockIdx.x * TT;

    // ---- stage x tile [TT x 128] (contiguous 32 KB)
    {
        const float* src = inputs + ((size_t)b * T_LEN + t0) * F_DIM;
        for (int i = tid; i < TT * F_DIM / 4; i += 400)
            cp16(&xs[0][0] + i * 4, src + i * 4);
        cp_commit();
        cp_wait_all();
    }
    __syncthreads();

    // ---- bias for owned 8 columns (as 4 float2)
    float2 bj[4];
    {
        const float2* b2 = (const float2*)bias;
        #pragma unroll
        for (int q = 0; q < 4; q++) bj[q] = __ldg(&b2[tj * 4 + q]);
    }

    float2 acc[4][4];                   // [k][q] — (t0+tt*4+k, j: tj*8+2q, +1)
    #pragma unroll
    for (int k = 0; k < 4; k++)
        #pragma unroll
        for (int q = 0; q < 4; q++) acc[k][q] = make_float2(0.f, 0.f);

    const float* xrow = &xs[tt * 4][0];
    const float4* wg  = (const float4*)(kernel + tj * 8);  // stride 200 floats per f

    #pragma unroll 4
    for (int f2 = 0; f2 < F_DIM / 2; f2++) {
        // x values for the 4 t-rows, 2 consecutive f each
        float2 xv[4];
        #pragma unroll
        for (int k = 0; k < 4; k++)
            xv[k] = *(const float2*)(xrow + k * F_DIM + 2 * f2);

        // weights for 8 columns, f = 2*f2 and 2*f2+1 (L2-resident)
        float4 wA0 = __ldg((const float4*)((const float*)wg + (2 * f2)     * Z_DIM));
        float4 wB0 = __ldg((const float4*)((const float*)wg + (2 * f2)     * Z_DIM + 4));
        float4 wA1 = __ldg((const float4*)((const float*)wg + (2 * f2 + 1) * Z_DIM));
        float4 wB1 = __ldg((const float4*)((const float*)wg + (2 * f2 + 1) * Z_DIM + 4));
        float2 w0[4] = { {wA0.x, wA0.y}, {wA0.z, wA0.w}, {wB0.x, wB0.y}, {wB0.z, wB0.w} };
        float2 w1[4] = { {wA1.x, wA1.y}, {wA1.z, wA1.w}, {wB1.x, wB1.y}, {wB1.z, wB1.w} };

        #pragma unroll
        for (int k = 0; k < 4; k++) {
            float2 xb0 = make_float2(xv[k].x, xv[k].x);
            float2 xb1 = make_float2(xv[k].y, xv[k].y);
            #pragma unroll
            for (int q = 0; q < 4; q++) {
                acc[k][q] = fma2(xb0, w0[q], acc[k][q]);
                acc[k][q] = fma2(xb1, w1[q], acc[k][q]);
            }
        }
    }

    // ---- epilogue: add bias, store 4 rows x 8 cols
    #pragma unroll
    for (int k = 0; k < 4; k++) {
        int t = t0 + tt * 4 + k;
        float* dst = g_zx + ((size_t)b * T_LEN + t) * Z_DIM + tj * 8;
        float4 o0, o1;
        o0.x = acc[k][0].x + bj[0].x;  o0.y = acc[k][0].y + bj[0].y;
        o0.z = acc[k][1].x + bj[1].x;  o0.w = acc[k][1].y + bj[1].y;
        o1.x = acc[k][2].x + bj[2].x;  o1.y = acc[k][2].y + bj[2].y;
        o1.z = acc[k][3].x + bj[3].x;  o1.w = acc[k][3].y + bj[3].y;
        *(float4*)dst       = o0;
        *(float4*)(dst + 4) = o1;
    }
}

// ============================================================
// Phase 2: recurrence. 128 CTAs x 256 threads, NB=4 batches/CTA.
// z[b][j] = Zx[b][t][j] + h[b] . rec_kernel[:, j]
// ============================================================
__global__ void __launch_bounds__(256, 1) lstm_rec_kernel(
    const float* __restrict__ rec_kernel,  // [U, 200]
    const float* __restrict__ dense_w,     // [U]
    const float* __restrict__ dense_b,     // [1]
    float* __restrict__ out)               // [B]
{
    __shared__ float zxs[DEPTH][NB][Z_DIM];  // 25.6 KB ring of Zx rows
    __shared__ float hs[NB][52];             // h, padded 50->52
    __shared__ float zs[NB][Z_DIM];          // gate pre-activations

    const int tid = threadIdx.x;
    const int b0  = blockIdx.x * NB;
    const int j   = tid;                     // owned z column (valid < 200)

    // rec_kernel[:, j] as 26 float2 (pairs over u; last pair zero-pad)
    float2 wr2[26];
    if (j < Z_DIM) {
        #pragma unroll
        for (int q = 0; q < 25; q++)
            wr2[q] = make_float2(rec_kernel[(2 * q)     * Z_DIM + j],
                                 rec_kernel[(2 * q + 1) * Z_DIM + j]);
        wr2[25] = make_float2(0.f, 0.f);
    }

    if (tid < NB * 52) ((float*)hs)[tid] = 0.f;

    float c_reg = 0.f;
    const int gu = tid % U_DIM;
    const int gb = tid / U_DIM;

    // cp.async source for this thread's 16B chunk of the Zx row
    const int pb = tid / 50;            // batch 0..3
    const int pc = tid % 50;            // 16B chunk within the 800B row
    const float* zsrc = g_zx + (size_t)(b0 + pb) * T_LEN * Z_DIM + pc * 4;

    // ---- prologue: prefetch t = 0..6 (7 groups)
    if (tid < Z_DIM) {
        for (int t = 0; t < DEPTH - 1; t++) {
            cp16(&zxs[t][pb][pc * 4], zsrc + (size_t)t * Z_DIM);
            cp_commit();
        }
    }
    __syncthreads();

    for (int t = 0; t < T_LEN; ++t) {
        // prefetch t+7, keep oldest (t) guaranteed complete
        if (tid < Z_DIM) {
            if (t + DEPTH - 1 < T_LEN)
                cp16(&zxs[(t + DEPTH - 1) & (DEPTH - 1)][pb][pc * 4],
                     zsrc + (size_t)(t + DEPTH - 1) * Z_DIM);
            cp_commit();
            cp_wait_7();
        }
        __syncthreads();   // zxs[t] visible; hs from prev step visible

        if (j < Z_DIM) {
            const int rb = t & (DEPTH - 1);
            float2 a0 = make_float2(zxs[rb][0][j], 0.f);
            float2 a1 = make_float2(zxs[rb][1][j], 0.f);
            float2 a2 = make_float2(zxs[rb][2][j], 0.f);
            float2 a3 = make_float2(zxs[rb][3][j], 0.f);

            const float4* h0 = (const float4*)hs[0];
            const float4* h1 = (const float4*)hs[1];
            const float4* h2 = (const float4*)hs[2];
            const float4* h3 = (const float4*)hs[3];
            #pragma unroll
            for (int q = 0; q < 13; q++) {
                float4 v0 = h0[q], v1 = h1[q], v2 = h2[q], v3 = h3[q];
                float2 w0 = wr2[2 * q], w1 = wr2[2 * q + 1];
                a0 = fma2(w0, make_float2(v0.x, v0.y), a0);
                a1 = fma2(w0, make_float2(v1.x, v1.y), a1);
                a2 = fma2(w0, make_float2(v2.x, v2.y), a2);
                a3 = fma2(w0, make_float2(v3.x, v3.y), a3);
                a0 = fma2(w1, make_float2(v0.z, v0.w), a0);
                a1 = fma2(w1, make_float2(v1.z, v1.w), a1);
                a2 = fma2(w1, make_float2(v2.z, v2.w), a2);
                a3 = fma2(w1, make_float2(v3.z, v3.w), a3);
            }
            zs[0][j] = a0.x + a0.y;
            zs[1][j] = a1.x + a1.y;
            zs[2][j] = a2.x + a2.y;
            zs[3][j] = a3.x + a3.y;
        }
        __syncthreads();

        // ---- gate phase
        if (tid < NB * U_DIM) {
            float zi = zs[gb][gu];
            float zf = zs[gb][U_DIM     + gu];
            float zg = zs[gb][2 * U_DIM + gu];
            float zo = zs[gb][3 * U_DIM + gu];
            float ig = sigm(zi);
            float fg = sigm(zf);
            float og = sigm(zo);
            float g  = tanh_fast(zg);
            c_reg = fg * c_reg + ig * g;
            hs[gb][gu] = og * tanh_fast(c_reg);
        }
    }
    __syncthreads();

    // ---- final dense
    if (tid < NB) {
        float acc = dense_b[0];
        #pragma unroll
        for (int u = 0; u < U_DIM; u++)
            acc += hs[tid][u] * dense_w[u];
        out[b0 + tid] = acc;
    }
}

extern "C" void kernel_launch(void* const* d_in, const int* in_sizes, int n_in,
                              void* d_out, int out_size) {
    const float* inputs     = (const float*)d_in[0];
    const float* kernel     = (const float*)d_in[1];
    const float* rec_kernel = (const float*)d_in[2];
    const float* bias       = (const float*)d_in[3];
    const float* dense_w    = (const float*)d_in[4];
    const float* dense_b    = (const float*)d_in[5];
    float* out = (float*)d_out;

    dim3 g1(T_LEN / TT, B_TOT);
    zx_gemm_kernel<<<g1, 400>>>(inputs, kernel, bias);
    lstm_rec_kernel<<<B_TOT / NB, 256>>>(rec_kernel, dense_w, dense_b, out);
}